// round 1
// baseline (speedup 1.0000x reference)
#include <cuda_runtime.h>

typedef unsigned long long u64;

#define KNB  16
#define FIN  7
#define FHID 40
#define FOUT 3
#define HP   20   // hidden pairs (40/2)

// ---- packed f32x2 helpers (ptxas never emits these from C++) ----
__device__ __forceinline__ u64 pk2(float lo, float hi) {
    u64 r; asm("mov.b64 %0, {%1,%2};" : "=l"(r) : "f"(lo), "f"(hi)); return r;
}
__device__ __forceinline__ void upk2(u64 v, float& lo, float& hi) {
    asm("mov.b64 {%0,%1}, %2;" : "=f"(lo), "=f"(hi) : "l"(v));
}
__device__ __forceinline__ u64 ffma2(u64 a, u64 b, u64 c) {
    u64 d; asm("fma.rn.f32x2 %0, %1, %2, %3;" : "=l"(d) : "l"(a), "l"(b), "l"(c)); return d;
}
__device__ __forceinline__ u64 fadd2(u64 a, u64 b) {
    u64 d; asm("add.rn.f32x2 %0, %1, %2;" : "=l"(d) : "l"(a), "l"(b)); return d;
}

// One thread per node. hidden units packed 2-wide in f32x2 lanes.
// h = relu(x@W1+b1) accumulated over k in hsum[20] (packed pairs),
// then y = (hsum/16)@W2 + b2  (mean/W2 commute since they're linear).
__global__ __launch_bounds__(128, 3)
void aggre_kernel(const float* __restrict__ mailbox,
                  const float* __restrict__ W1,
                  const float* __restrict__ b1,
                  const float* __restrict__ W2,
                  const float* __restrict__ b2,
                  float* __restrict__ out,
                  int n_nodes)
{
    // s_w1[hp][f=0..6] = (W1[f][2hp], W1[f][2hp+1]); s_w1[hp][7] = (b1[2hp], b1[2hp+1])
    __shared__ __align__(16) float2 s_w1[HP][8];
    __shared__ float2 s_w2[HP][4];   // [hp][o] = (W2[2hp][o], W2[2hp+1][o]); [3] pad
    __shared__ float  s_b2[FOUT];

    for (int i = threadIdx.x; i < HP * 8; i += blockDim.x) {
        int hp = i >> 3, f = i & 7;
        float lo, hi;
        if (f < FIN) { lo = W1[f * FHID + 2 * hp]; hi = W1[f * FHID + 2 * hp + 1]; }
        else         { lo = b1[2 * hp];            hi = b1[2 * hp + 1]; }
        s_w1[hp][f] = make_float2(lo, hi);
    }
    for (int i = threadIdx.x; i < HP * FOUT; i += blockDim.x) {
        int hp = i / FOUT, o = i - hp * FOUT;
        s_w2[hp][o] = make_float2(W2[(2 * hp) * FOUT + o], W2[(2 * hp + 1) * FOUT + o]);
    }
    if (threadIdx.x < FOUT) s_b2[threadIdx.x] = b2[threadIdx.x];
    __syncthreads();

    int n = blockIdx.x * blockDim.x + threadIdx.x;
    if (n >= n_nodes) return;

    // node's mailbox: 16*7 = 112 floats = 28 float4 (448B, 16B-aligned per node)
    const float4* mb = reinterpret_cast<const float4*>(mailbox) + (size_t)n * 28;

    u64 hsum[HP];
    #pragma unroll
    for (int hp = 0; hp < HP; hp++) hsum[hp] = 0ULL;   // packed (0,0)

    // 4 chunks x 4 messages; chunk loop NOT unrolled (code size / reg pressure)
    #pragma unroll 1
    for (int kc = 0; kc < 4; kc++) {
        // 4 messages = 28 floats = 7 float4
        float4 xr[7];
        #pragma unroll
        for (int i = 0; i < 7; i++) xr[i] = mb[kc * 7 + i];

        // duplicate each scalar into both f32x2 lanes (reused across all 20 hp)
        u64 xd[28];
        #pragma unroll
        for (int i = 0; i < 7; i++) {
            xd[4 * i + 0] = pk2(xr[i].x, xr[i].x);
            xd[4 * i + 1] = pk2(xr[i].y, xr[i].y);
            xd[4 * i + 2] = pk2(xr[i].z, xr[i].z);
            xd[4 * i + 3] = pk2(xr[i].w, xr[i].w);
        }

        #pragma unroll
        for (int hp = 0; hp < HP; hp++) {
            // 4x LDS.128 broadcast: 7 weight pairs + bias pair for this hp
            const ulonglong2* wrow = reinterpret_cast<const ulonglong2*>(&s_w1[hp][0]);
            ulonglong2 p0 = wrow[0], p1 = wrow[1], p2 = wrow[2], p3 = wrow[3];
            u64 w[7] = { p0.x, p0.y, p1.x, p1.y, p2.x, p2.y, p3.x };
            u64 bp = p3.y;
            #pragma unroll
            for (int j = 0; j < 4; j++) {
                u64 a = bp;
                #pragma unroll
                for (int f = 0; f < FIN; f++)
                    a = ffma2(xd[7 * j + f], w[f], a);     // 7 FFMA2: 14 MACs
                float ax, ay; upk2(a, ax, ay);
                // ReLU on ALU pipe (FMNMX), re-pack, accumulate on fma pipe
                hsum[hp] = fadd2(hsum[hp], pk2(fmaxf(ax, 0.f), fmaxf(ay, 0.f)));
            }
        }
    }

    // second layer on the k-summed hidden, then scale by 1/16 and add b2
    float y0 = 0.f, y1 = 0.f, y2 = 0.f;
    #pragma unroll
    for (int hp = 0; hp < HP; hp++) {
        float hx, hy; upk2(hsum[hp], hx, hy);
        float2 c0 = s_w2[hp][0], c1 = s_w2[hp][1], c2 = s_w2[hp][2];
        y0 = fmaf(hx, c0.x, y0); y0 = fmaf(hy, c0.y, y0);
        y1 = fmaf(hx, c1.x, y1); y1 = fmaf(hy, c1.y, y1);
        y2 = fmaf(hx, c2.x, y2); y2 = fmaf(hy, c2.y, y2);
    }
    const float inv = 1.0f / 16.0f;
    float* o = out + (size_t)n * FOUT;
    o[0] = fmaf(y0, inv, s_b2[0]);
    o[1] = fmaf(y1, inv, s_b2[1]);
    o[2] = fmaf(y2, inv, s_b2[2]);
}

extern "C" void kernel_launch(void* const* d_in, const int* in_sizes, int n_in,
                              void* d_out, int out_size)
{
    const float* mailbox = (const float*)d_in[0];
    const float* W1      = (const float*)d_in[1];
    const float* b1      = (const float*)d_in[2];
    const float* W2      = (const float*)d_in[3];
    const float* b2      = (const float*)d_in[4];
    float* out = (float*)d_out;

    int n_nodes = in_sizes[0] / (KNB * FIN);
    int threads = 128;
    int blocks  = (n_nodes + threads - 1) / threads;
    aggre_kernel<<<blocks, threads>>>(mailbox, W1, b1, W2, b2, out, n_nodes);
}

// round 4
// speedup vs baseline: 4.5982x; 4.5982x over previous
#include <cuda_runtime.h>

typedef unsigned long long u64;

#define KNB   16
#define FIN   7
#define FHID  40
#define FOUT  3
#define HP    20          // hidden pairs (40/2)
#define HPG   4           // hidden pairs per register group
#define NGRP  (HP/HPG)    // 5 groups
#define TILE  128         // nodes per block
#define NF4   28          // float4 per node (16*7 floats)
#define STR   29          // padded float4 stride in smem (29 mod 8 = 5 -> conflict-free)

// ---- packed f32x2 helpers ----
__device__ __forceinline__ u64 pk2(float lo, float hi) {
    u64 r; asm("mov.b64 %0, {%1,%2};" : "=l"(r) : "f"(lo), "f"(hi)); return r;
}
__device__ __forceinline__ void upk2(u64 v, float& lo, float& hi) {
    asm("mov.b64 {%0,%1}, %2;" : "=f"(lo), "=f"(hi) : "l"(v));
}
__device__ __forceinline__ u64 ffma2(u64 a, u64 b, u64 c) {
    u64 d; asm("fma.rn.f32x2 %0, %1, %2, %3;" : "=l"(d) : "l"(a), "l"(b), "l"(c)); return d;
}
__device__ __forceinline__ u64 fadd2(u64 a, u64 b) {
    u64 d; asm("add.rn.f32x2 %0, %1, %2;" : "=l"(d) : "l"(a), "l"(b)); return d;
}
__device__ __forceinline__ unsigned smem_u32(const void* p) {
    unsigned a;
    asm("{ .reg .u64 t; cvta.to.shared.u64 t, %1; cvt.u32.u64 %0, t; }" : "=r"(a) : "l"(p));
    return a;
}
__device__ __forceinline__ void cp_async16(unsigned dst, const void* src) {
    asm volatile("cp.async.cg.shared.global [%0], [%1], 16;" :: "r"(dst), "l"(src));
}

// dynamic smem layout:
//   [0 .. TILE*STR)                  float4 staged mailbox tile (padded stride)
//   then: s_w1[HP][8] float2  (7 weight pairs + bias pair per hp)
//         s_w2[HP][3] float2  (W2 pairs)
//         s_b2[4]     float
#define SMEM_X_F4   (TILE*STR)
#define SMEM_BYTES  (SMEM_X_F4*16 + HP*8*8 + HP*3*8 + 4*4)

__global__ __launch_bounds__(128, 3)
void aggre_kernel(const float* __restrict__ mailbox,
                  const float* __restrict__ W1,
                  const float* __restrict__ b1,
                  const float* __restrict__ W2,
                  const float* __restrict__ b2,
                  float* __restrict__ out,
                  int n_nodes)
{
    extern __shared__ __align__(16) float4 smem[];
    float4* s_x  = smem;
    float2* s_w1 = reinterpret_cast<float2*>(smem + SMEM_X_F4);       // [HP][8]
    float2* s_w2 = s_w1 + HP * 8;                                     // [HP][3]
    float*  s_b2 = reinterpret_cast<float*>(s_w2 + HP * 3);

    const int tid   = threadIdx.x;
    const int nbase = blockIdx.x * TILE;
    const int nval  = min(TILE, n_nodes - nbase);

    // ---- stage weights (tiny) ----
    for (int i = tid; i < HP * 8; i += 128) {
        int hp = i >> 3, f = i & 7;
        float lo, hi;
        if (f < FIN) { lo = W1[f * FHID + 2 * hp]; hi = W1[f * FHID + 2 * hp + 1]; }
        else         { lo = b1[2 * hp];            hi = b1[2 * hp + 1]; }
        s_w1[i] = make_float2(lo, hi);
    }
    for (int i = tid; i < HP * FOUT; i += 128) {
        int hp = i / FOUT, o = i - hp * FOUT;
        s_w2[i] = make_float2(W2[(2 * hp) * FOUT + o], W2[(2 * hp + 1) * FOUT + o]);
    }
    if (tid < FOUT) s_b2[tid] = b2[tid];

    // ---- stage mailbox tile: coalesced cp.async, padded smem stride ----
    {
        const float4* src = reinterpret_cast<const float4*>(mailbox) + (size_t)nbase * NF4;
        unsigned xb = smem_u32(s_x);
        int total = nval * NF4;
        #pragma unroll
        for (int it = 0; it < NF4; it++) {              // 28 iters of 128 threads
            int g = it * 128 + tid;
            if (g < total) {
                int i = g / NF4;
                int j = g - i * NF4;
                cp_async16(xb + (unsigned)(i * STR + j) * 16u, src + g);
            }
        }
        asm volatile("cp.async.commit_group;");
        asm volatile("cp.async.wait_group 0;");
    }
    __syncthreads();

    // ---- per-node compute ----
    const int i = tid;
    if (nbase + i < n_nodes) {
        const float4* xrow = s_x + i * STR;
        const ulonglong2* w1v = reinterpret_cast<const ulonglong2*>(s_w1);
        const u64* w2v = reinterpret_cast<const u64*>(s_w2);

        u64 y[FOUT] = {0ULL, 0ULL, 0ULL};

        #pragma unroll 1
        for (int hpg = 0; hpg < NGRP; hpg++) {
            // weights for 4 hidden-pairs of this group
            u64 w[HPG][FIN], bp[HPG];
            #pragma unroll
            for (int h = 0; h < HPG; h++) {
                const ulonglong2* row = w1v + (hpg * HPG + h) * 4;
                ulonglong2 p0 = row[0], p1 = row[1], p2 = row[2], p3 = row[3];
                w[h][0] = p0.x; w[h][1] = p0.y; w[h][2] = p1.x; w[h][3] = p1.y;
                w[h][4] = p2.x; w[h][5] = p2.y; w[h][6] = p3.x; bp[h] = p3.y;
            }

            u64 hs[HPG] = {0ULL, 0ULL, 0ULL, 0ULL};

            #pragma unroll
            for (int kc = 0; kc < 4; kc++) {            // 4 chunks x 4 messages
                // load 28 floats (4 messages) and duplicate into f32x2 lanes
                u64 xd[28];
                #pragma unroll
                for (int t = 0; t < 7; t++) {
                    float4 v = xrow[kc * 7 + t];
                    xd[4 * t + 0] = pk2(v.x, v.x);
                    xd[4 * t + 1] = pk2(v.y, v.y);
                    xd[4 * t + 2] = pk2(v.z, v.z);
                    xd[4 * t + 3] = pk2(v.w, v.w);
                }
                #pragma unroll
                for (int h = 0; h < HPG; h++) {
                    #pragma unroll
                    for (int j = 0; j < 4; j++) {
                        u64 a = bp[h];
                        #pragma unroll
                        for (int f = 0; f < FIN; f++)
                            a = ffma2(xd[7 * j + f], w[h][f], a);
                        float ax, ay; upk2(a, ax, ay);
                        hs[h] = fadd2(hs[h], pk2(fmaxf(ax, 0.f), fmaxf(ay, 0.f)));
                    }
                }
            }

            // fold this group's hidden sums into packed outputs
            #pragma unroll
            for (int h = 0; h < HPG; h++) {
                int hp = hpg * HPG + h;
                #pragma unroll
                for (int o = 0; o < FOUT; o++)
                    y[o] = ffma2(hs[h], w2v[hp * FOUT + o], y[o]);
            }
        }

        const float inv = 1.0f / 16.0f;
        float* op = out + (size_t)(nbase + i) * FOUT;
        #pragma unroll
        for (int o = 0; o < FOUT; o++) {
            float lo, hi; upk2(y[o], lo, hi);
            op[o] = fmaf(lo + hi, inv, s_b2[o]);
        }
    }
}

extern "C" void kernel_launch(void* const* d_in, const int* in_sizes, int n_in,
                              void* d_out, int out_size)
{
    const float* mailbox = (const float*)d_in[0];
    const float* W1      = (const float*)d_in[1];
    const float* b1      = (const float*)d_in[2];
    const float* W2      = (const float*)d_in[3];
    const float* b2      = (const float*)d_in[4];
    float* out = (float*)d_out;

    int n_nodes = in_sizes[0] / (KNB * FIN);
    int blocks  = (n_nodes + TILE - 1) / TILE;

    static bool attr_set = false;
    if (!attr_set) {
        cudaFuncSetAttribute(aggre_kernel,
                             cudaFuncAttributeMaxDynamicSharedMemorySize, SMEM_BYTES);
        attr_set = true;
    }
    aggre_kernel<<<blocks, 128, SMEM_BYTES>>>(mailbox, W1, b1, W2, b2, out, n_nodes);
}